// round 1
// baseline (speedup 1.0000x reference)
#include <cuda_runtime.h>
#include <cuda_bf16.h>

// Problem constants (from reference)
#define NUM_GENES 20000
#define NUM_FEAT  256
#define BATCH     32
#define VOCAB     9
#define F4_PER_ROW (NUM_FEAT / 4)          // 64 float4 per row
#define TOTAL_ROWS (BATCH * NUM_GENES)     // 640000
#define TOTAL_F4   ((long long)TOTAL_ROWS * F4_PER_ROW)  // 40,960,000 (< 2^31)

// Scratch: membership mask over gene positions (no cudaMalloc allowed)
__device__ unsigned char g_masked[NUM_GENES];

__global__ void clear_mask_kernel() {
    int i = blockIdx.x * blockDim.x + threadIdx.x;
    if (i < NUM_GENES) g_masked[i] = 0;
}

__global__ void set_mask_kernel(const int* __restrict__ geneset, int n) {
    int i = blockIdx.x * blockDim.x + threadIdx.x;
    if (i < n) {
        int g = geneset[i];
        if (g >= 0 && g < NUM_GENES) g_masked[g] = 1;
    }
}

// Main fused kernel: out[b,g,f] = gene_table[g,f] + mut_table[tok(b,g), f]
// tok(b,g) = masked[g] ? VOCAB-1 : X[b,g]
// One thread per float4 (4 features). 256 threads/block.
__global__ __launch_bounds__(256)
void fuse_kernel(const int* __restrict__ X,
                 const float4* __restrict__ gene,   // [NUM_GENES * 64]
                 const float4* __restrict__ mut,    // [VOCAB * 64]
                 float4* __restrict__ out)          // [TOTAL_ROWS * 64]
{
    // Stage mut_table (9 * 64 float4 = 9216 B) into shared memory
    __shared__ float4 smut[VOCAB * F4_PER_ROW];
    #pragma unroll
    for (int i = threadIdx.x; i < VOCAB * F4_PER_ROW; i += 256)
        smut[i] = mut[i];
    __syncthreads();

    int t = blockIdx.x * 256 + threadIdx.x;     // < 40,960,000, fits int
    int r = t >> 6;                             // row index = b*NUM_GENES + g
    int f = t & (F4_PER_ROW - 1);               // float4 index within row
    int g = r % NUM_GENES;

    int tok = g_masked[g] ? (VOCAB - 1) : X[r];

    float4 a = gene[g * F4_PER_ROW + f];
    float4 m = smut[tok * F4_PER_ROW + f];

    float4 o;
    o.x = a.x + m.x;
    o.y = a.y + m.y;
    o.z = a.z + m.z;
    o.w = a.w + m.w;
    out[t] = o;
}

extern "C" void kernel_launch(void* const* d_in, const int* in_sizes, int n_in,
                              void* d_out, int out_size) {
    // metadata order: X_converted, mask_percentage, test_geneset, gene_table, mut_table
    const int*   X        = (const int*)d_in[0];
    const int*   geneset  = (const int*)d_in[2];
    const float* gene     = (const float*)d_in[3];
    const float* mut      = (const float*)d_in[4];
    float*       out      = (float*)d_out;
    int n_mask = in_sizes[2];

    clear_mask_kernel<<<(NUM_GENES + 255) / 256, 256>>>();
    set_mask_kernel<<<(n_mask + 255) / 256, 256>>>(geneset, n_mask);

    int total_f4 = (int)TOTAL_F4;              // 40,960,000
    int blocks = total_f4 / 256;               // 160,000 exact
    fuse_kernel<<<blocks, 256>>>(X,
                                 (const float4*)gene,
                                 (const float4*)mut,
                                 (float4*)out);
}

// round 2
// speedup vs baseline: 1.3892x; 1.3892x over previous
#include <cuda_runtime.h>
#include <cuda_bf16.h>

#define NUM_GENES 20000
#define NUM_FEAT  256
#define BATCH     32
#define VOCAB     9
#define F4_PER_ROW (NUM_FEAT / 4)            // 64 float4 per row
#define GENES_PER_BLOCK 4                    // 256 threads = 4 genes * 64 f4-lanes
#define ROW_STRIDE_F4 (NUM_GENES * F4_PER_ROW)  // 1,280,000 float4 per batch

// Scratch: membership mask over gene positions (no cudaMalloc allowed)
__device__ unsigned char g_masked[NUM_GENES];

__global__ void clear_mask_kernel() {
    int i = blockIdx.x * blockDim.x + threadIdx.x;
    if (i < NUM_GENES) g_masked[i] = 0;
}

__global__ void set_mask_kernel(const int* __restrict__ geneset, int n) {
    int i = blockIdx.x * blockDim.x + threadIdx.x;
    if (i < n) {
        int g = geneset[i];
        if (g >= 0 && g < NUM_GENES) g_masked[g] = 1;
    }
}

// Each block: GENES_PER_BLOCK genes, all 32 batches.
// Thread (gl, f): holds gene_table[g][4f..4f+3] in a register, loops over b.
// Gene L2 traffic drops 32x vs the naive mapping; LTS now carries only the
// unavoidable 655 MB of stores (+20.5 MB gene reads + 2.5 MB token reads).
__global__ __launch_bounds__(256)
void fuse_kernel(const int* __restrict__ X,          // [BATCH * NUM_GENES]
                 const float4* __restrict__ gene,    // [NUM_GENES * 64]
                 const float4* __restrict__ mut,     // [VOCAB * 64]
                 float4* __restrict__ out)           // [BATCH*NUM_GENES*64]
{
    __shared__ float4 smut[VOCAB * F4_PER_ROW];            // 9216 B
    __shared__ int    stok[BATCH * GENES_PER_BLOCK];       // pre-masked tokens

    int tid = threadIdx.x;
    int g_base = blockIdx.x * GENES_PER_BLOCK;

    // Stage mut_table
    #pragma unroll
    for (int i = tid; i < VOCAB * F4_PER_ROW; i += 256)
        smut[i] = mut[i];

    // Stage tokens for (b, gl), applying the mask up-front.
    if (tid < BATCH * GENES_PER_BLOCK) {
        int b  = tid >> 2;          // 0..31
        int gl = tid & 3;           // 0..3
        int g  = g_base + gl;
        int tok = g_masked[g] ? (VOCAB - 1) : X[b * NUM_GENES + g];
        stok[tid] = tok;
    }
    __syncthreads();

    int gl = tid >> 6;              // gene within block (0..3)
    int f  = tid & (F4_PER_ROW - 1);
    int g  = g_base + gl;

    // Gene embedding float4 lives in registers for all 32 batches.
    float4 a = gene[g * F4_PER_ROW + f];

    int out_base = g * F4_PER_ROW + f;

    #pragma unroll 8
    for (int b = 0; b < BATCH; b++) {
        int tok = stok[(b << 2) | gl];          // uniform within warp -> LDS broadcast
        float4 m = smut[tok * F4_PER_ROW + f];
        float4 o;
        o.x = a.x + m.x;
        o.y = a.y + m.y;
        o.z = a.z + m.z;
        o.w = a.w + m.w;
        out[out_base + b * ROW_STRIDE_F4] = o;
    }
}

extern "C" void kernel_launch(void* const* d_in, const int* in_sizes, int n_in,
                              void* d_out, int out_size) {
    // metadata order: X_converted, mask_percentage, test_geneset, gene_table, mut_table
    const int*   X        = (const int*)d_in[0];
    const int*   geneset  = (const int*)d_in[2];
    const float* gene     = (const float*)d_in[3];
    const float* mut      = (const float*)d_in[4];
    float*       out      = (float*)d_out;
    int n_mask = in_sizes[2];

    clear_mask_kernel<<<(NUM_GENES + 255) / 256, 256>>>();
    set_mask_kernel<<<(n_mask + 255) / 256, 256>>>(geneset, n_mask);

    int blocks = NUM_GENES / GENES_PER_BLOCK;   // 5000 exact
    fuse_kernel<<<blocks, 256>>>(X,
                                 (const float4*)gene,
                                 (const float4*)mut,
                                 (float4*)out);
}

// round 3
// speedup vs baseline: 1.7563x; 1.2643x over previous
#include <cuda_runtime.h>
#include <cuda_bf16.h>

#define NUM_GENES 20000
#define NUM_FEAT  256
#define BATCH     32
#define VOCAB     9
#define F4_PER_ROW (NUM_FEAT / 4)               // 64 float4 per row
#define GENES_PER_BLOCK 4
#define BATCH_GROUPS 4                          // batch loop split 4-ways
#define BATCH_PER_GROUP (BATCH / BATCH_GROUPS)  // 8
#define GENE_GROUPS (NUM_GENES / GENES_PER_BLOCK)  // 5000
#define ROW_STRIDE_F4 (NUM_GENES * F4_PER_ROW)     // 1,280,000 float4 per batch

// Scratch: membership mask over gene positions (no cudaMalloc allowed)
__device__ unsigned char g_masked[NUM_GENES];

// Single prologue kernel: mask[g] = (g in geneset). Each block stages the
// geneset in shared and every thread scans it with int4 LDS broadcasts.
__global__ __launch_bounds__(256)
void build_mask_kernel(const int* __restrict__ geneset, int n) {
    __shared__ int sgs[2048];                   // up to 8 KB of geneset ids
    int tid = threadIdx.x;
    int n_sh = n < 2048 ? n : 2048;
    for (int i = tid; i < n_sh; i += 256) sgs[i] = geneset[i];
    __syncthreads();

    int g = blockIdx.x * 256 + tid;
    if (g >= NUM_GENES) return;

    bool hit = false;
    int n4 = n_sh & ~3;
    const int4* sgs4 = (const int4*)sgs;
    for (int i = 0; i < n4 / 4; i++) {          // warp-uniform -> LDS broadcast
        int4 v = sgs4[i];
        hit |= (v.x == g) | (v.y == g) | (v.z == g) | (v.w == g);
    }
    for (int i = n4; i < n_sh; i++) hit |= (sgs[i] == g);
    // Overflow path (n > 2048): scan the rest from global (L2-resident)
    for (int i = 2048; i < n; i++) hit |= (geneset[i] == g);

    g_masked[g] = hit ? 1 : 0;
}

// Main kernel: block = (4 genes) x (8 batches). Thread (gl,f) holds
// gene_table[g][4f..4f+3] in a register across its 8 batch stores.
__global__ __launch_bounds__(256)
void fuse_kernel(const int* __restrict__ X,          // [BATCH * NUM_GENES]
                 const float4* __restrict__ gene,    // [NUM_GENES * 64]
                 const float4* __restrict__ mut,     // [VOCAB * 64]
                 float4* __restrict__ out)           // [BATCH*NUM_GENES*64]
{
    __shared__ float4 smut[VOCAB * F4_PER_ROW];              // 9216 B
    __shared__ int    stok[BATCH_PER_GROUP * GENES_PER_BLOCK];

    int tid = threadIdx.x;
    int gq  = blockIdx.x % GENE_GROUPS;          // gene quad index
    int bg  = blockIdx.x / GENE_GROUPS;          // batch group 0..3
    int g_base = gq * GENES_PER_BLOCK;
    int b_base = bg * BATCH_PER_GROUP;

    #pragma unroll
    for (int i = tid; i < VOCAB * F4_PER_ROW; i += 256)
        smut[i] = mut[i];

    if (tid < BATCH_PER_GROUP * GENES_PER_BLOCK) {           // 32 threads
        int bl = tid >> 2;                                   // 0..7
        int gl = tid & 3;
        int g  = g_base + gl;
        int tok = g_masked[g] ? (VOCAB - 1)
                              : X[(b_base + bl) * NUM_GENES + g];
        stok[tid] = tok;
    }
    __syncthreads();

    int gl = tid >> 6;                 // gene within block (0..3)
    int f  = tid & (F4_PER_ROW - 1);   // float4 lane within row
    int g  = g_base + gl;

    float4 a = gene[g * F4_PER_ROW + f];     // register-resident, reused 8x

    long long out_base = (long long)(b_base) * ROW_STRIDE_F4
                       + g * F4_PER_ROW + f;

    #pragma unroll
    for (int bl = 0; bl < BATCH_PER_GROUP; bl++) {
        int tok = stok[(bl << 2) | gl];            // warp-uniform broadcast
        float4 m = smut[tok * F4_PER_ROW + f];
        float4 o;
        o.x = a.x + m.x;
        o.y = a.y + m.y;
        o.z = a.z + m.z;
        o.w = a.w + m.w;
        __stcs(&out[out_base + (long long)bl * ROW_STRIDE_F4], o);
    }
}

extern "C" void kernel_launch(void* const* d_in, const int* in_sizes, int n_in,
                              void* d_out, int out_size) {
    // metadata order: X_converted, mask_percentage, test_geneset, gene_table, mut_table
    const int*   X        = (const int*)d_in[0];
    const int*   geneset  = (const int*)d_in[2];
    const float* gene     = (const float*)d_in[3];
    const float* mut      = (const float*)d_in[4];
    float*       out      = (float*)d_out;
    int n_mask = in_sizes[2];

    build_mask_kernel<<<(NUM_GENES + 255) / 256, 256>>>(geneset, n_mask);

    int blocks = GENE_GROUPS * BATCH_GROUPS;     // 20000
    fuse_kernel<<<blocks, 256>>>(X,
                                 (const float4*)gene,
                                 (const float4*)mut,
                                 (float4*)out);
}

// round 4
// speedup vs baseline: 1.8432x; 1.0495x over previous
#include <cuda_runtime.h>
#include <cuda_bf16.h>

#define NUM_GENES 20000
#define NUM_FEAT  256
#define BATCH     32
#define VOCAB     9
#define F4_PER_ROW (NUM_FEAT / 4)               // 64 float4 per row
#define GENES_PER_BLOCK 8
#define THREADS   512                           // 8 genes * 64 f4-lanes
#define BATCH_GROUPS 4
#define BATCH_PER_GROUP (BATCH / BATCH_GROUPS)  // 8
#define GENE_GROUPS (NUM_GENES / GENES_PER_BLOCK)  // 2500
#define ROW_STRIDE_F4 (NUM_GENES * F4_PER_ROW)     // 1,280,000 float4 per batch

// Single fused kernel:
//  Phase A (overlapped): stage mut_table in smem; scan geneset for membership
//    of this block's 8 genes (strided int4 loads, L2-resident, ~free under
//    the memory-bound mainloop's idle issue slots).
//  Phase B: 8 genes x 8 batches of  out = gene_reg + smut[tok]  float4 stores.
__global__ __launch_bounds__(THREADS)
void fuse_kernel(const int* __restrict__ X,          // [BATCH * NUM_GENES]
                 const float4* __restrict__ gene,    // [NUM_GENES * 64]
                 const float4* __restrict__ mut,     // [VOCAB * 64]
                 const int* __restrict__ geneset,    // [n_mask]
                 int n_mask,
                 float4* __restrict__ out)           // [BATCH*NUM_GENES*64]
{
    __shared__ float4 smut[VOCAB * F4_PER_ROW];              // 9216 B
    __shared__ int    stok[BATCH_PER_GROUP * GENES_PER_BLOCK]; // 64 tokens
    __shared__ unsigned int shit;                            // hit bit per gene

    int tid = threadIdx.x;
    int gq  = blockIdx.x % GENE_GROUPS;
    int bg  = blockIdx.x / GENE_GROUPS;
    int g_base = gq * GENES_PER_BLOCK;
    int b_base = bg * BATCH_PER_GROUP;

    if (tid == 0) shit = 0;

    // Stage mut_table (9 KB)
    #pragma unroll
    for (int i = tid; i < VOCAB * F4_PER_ROW; i += THREADS)
        smut[i] = mut[i];

    // Membership scan: does geneset contain any of genes [g_base, g_base+8)?
    unsigned int local = 0;
    int n4 = n_mask >> 2;
    const int4* gs4 = (const int4*)geneset;
    for (int i = tid; i < n4; i += THREADS) {
        int4 v = gs4[i];
        int d;
        d = v.x - g_base; if ((unsigned)d < GENES_PER_BLOCK) local |= 1u << d;
        d = v.y - g_base; if ((unsigned)d < GENES_PER_BLOCK) local |= 1u << d;
        d = v.z - g_base; if ((unsigned)d < GENES_PER_BLOCK) local |= 1u << d;
        d = v.w - g_base; if ((unsigned)d < GENES_PER_BLOCK) local |= 1u << d;
    }
    for (int i = (n4 << 2) + tid; i < n_mask; i += THREADS) {
        int d = geneset[i] - g_base;
        if ((unsigned)d < GENES_PER_BLOCK) local |= 1u << d;
    }
    // Hits are rare (~0.8 expected per block) -> atomicOr only when nonzero
    local |= __shfl_xor_sync(0xFFFFFFFFu, local, 16);
    local |= __shfl_xor_sync(0xFFFFFFFFu, local, 8);
    local |= __shfl_xor_sync(0xFFFFFFFFu, local, 4);
    local |= __shfl_xor_sync(0xFFFFFFFFu, local, 2);
    local |= __shfl_xor_sync(0xFFFFFFFFu, local, 1);
    if ((tid & 31) == 0 && local) atomicOr(&shit, local);
    __syncthreads();

    // Stage pre-masked tokens for (bl, gl)
    unsigned int hits = shit;
    if (tid < BATCH_PER_GROUP * GENES_PER_BLOCK) {           // 64 threads
        int bl = tid >> 3;                                   // 0..7
        int gl = tid & 7;                                    // 0..7
        int g  = g_base + gl;
        int tok = ((hits >> gl) & 1u) ? (VOCAB - 1)
                                      : X[(b_base + bl) * NUM_GENES + g];
        stok[tid] = tok;
    }
    __syncthreads();

    int gl = tid >> 6;                 // gene within block (0..7)
    int f  = tid & (F4_PER_ROW - 1);   // float4 lane within row
    int g  = g_base + gl;

    float4 a = gene[g * F4_PER_ROW + f];     // register-resident, reused 8x

    long long out_base = (long long)b_base * ROW_STRIDE_F4
                       + g * F4_PER_ROW + f;

    #pragma unroll
    for (int bl = 0; bl < BATCH_PER_GROUP; bl++) {
        int tok = stok[(bl << 3) | gl];            // warp-uniform broadcast
        float4 m = smut[tok * F4_PER_ROW + f];
        float4 o;
        o.x = a.x + m.x;
        o.y = a.y + m.y;
        o.z = a.z + m.z;
        o.w = a.w + m.w;
        __stcs(&out[out_base + (long long)bl * ROW_STRIDE_F4], o);
    }
}

extern "C" void kernel_launch(void* const* d_in, const int* in_sizes, int n_in,
                              void* d_out, int out_size) {
    // metadata order: X_converted, mask_percentage, test_geneset, gene_table, mut_table
    const int*   X        = (const int*)d_in[0];
    const int*   geneset  = (const int*)d_in[2];
    const float* gene     = (const float*)d_in[3];
    const float* mut      = (const float*)d_in[4];
    float*       out      = (float*)d_out;
    int n_mask = in_sizes[2];

    int blocks = GENE_GROUPS * BATCH_GROUPS;     // 10000
    fuse_kernel<<<blocks, THREADS>>>(X,
                                     (const float4*)gene,
                                     (const float4*)mut,
                                     geneset, n_mask,
                                     (float4*)out);
}

// round 8
// speedup vs baseline: 1.9304x; 1.0473x over previous
#include <cuda_runtime.h>
#include <cuda_bf16.h>

#define NUM_GENES 20000
#define NUM_FEAT  256
#define BATCH     32
#define VOCAB     9
#define F4_PER_ROW (NUM_FEAT / 4)               // 64 float4 per row
#define GENES_PER_BLOCK 8
#define THREADS   512                           // 8 genes * 64 f4-lanes
#define BATCH_GROUPS 2
#define BATCH_PER_GROUP (BATCH / BATCH_GROUPS)  // 16
#define GENE_GROUPS (NUM_GENES / GENES_PER_BLOCK)  // 2500
#define ROW_STRIDE_F4 (NUM_GENES * F4_PER_ROW)     // 1,280,000 float4 per batch

// Single fused kernel:
//  Phase A: stage mut_table in smem; scan the (L2-resident) geneset for
//    membership of this block's 8 genes; stage pre-masked tokens.
//    NOTE: shit init is barrier-separated from the atomicOr consumers —
//    the R5 failure was an init/atomicOr race under graph replay.
//  Phase B: 8 genes x 16 batches of  out = gene_reg + smut[tok]  STG.128.cs.
__global__ __launch_bounds__(THREADS)
void fuse_kernel(const int* __restrict__ X,          // [BATCH * NUM_GENES]
                 const float4* __restrict__ gene,    // [NUM_GENES * 64]
                 const float4* __restrict__ mut,     // [VOCAB * 64]
                 const int* __restrict__ geneset,    // [n_mask]
                 int n_mask,
                 float4* __restrict__ out)           // [BATCH*NUM_GENES*64]
{
    __shared__ float4 smut[VOCAB * F4_PER_ROW];                 // 9216 B
    __shared__ int    stok[BATCH_PER_GROUP * GENES_PER_BLOCK];  // 128 tokens
    __shared__ unsigned int shit;                               // hit bits

    int tid = threadIdx.x;
    int gq  = blockIdx.x % GENE_GROUPS;
    int bg  = blockIdx.x / GENE_GROUPS;
    int g_base = gq * GENES_PER_BLOCK;
    int b_base = bg * BATCH_PER_GROUP;

    if (tid == 0) shit = 0;

    // Stage mut_table (9 KB)
    #pragma unroll
    for (int i = tid; i < VOCAB * F4_PER_ROW; i += THREADS)
        smut[i] = mut[i];

    // BARRIER: shit=0 must be globally visible before any warp's atomicOr.
    __syncthreads();

    // Membership scan over geneset for genes [g_base, g_base+8)
    unsigned int local = 0;
    int n4 = n_mask >> 2;
    const int4* gs4 = (const int4*)geneset;
    for (int i = tid; i < n4; i += THREADS) {
        int4 v = gs4[i];
        int d;
        d = v.x - g_base; if ((unsigned)d < GENES_PER_BLOCK) local |= 1u << d;
        d = v.y - g_base; if ((unsigned)d < GENES_PER_BLOCK) local |= 1u << d;
        d = v.z - g_base; if ((unsigned)d < GENES_PER_BLOCK) local |= 1u << d;
        d = v.w - g_base; if ((unsigned)d < GENES_PER_BLOCK) local |= 1u << d;
    }
    for (int i = (n4 << 2) + tid; i < n_mask; i += THREADS) {
        int d = geneset[i] - g_base;
        if ((unsigned)d < GENES_PER_BLOCK) local |= 1u << d;
    }
    // Hits are rare -> warp-reduce, atomicOr only when nonzero
    local |= __shfl_xor_sync(0xFFFFFFFFu, local, 16);
    local |= __shfl_xor_sync(0xFFFFFFFFu, local, 8);
    local |= __shfl_xor_sync(0xFFFFFFFFu, local, 4);
    local |= __shfl_xor_sync(0xFFFFFFFFu, local, 2);
    local |= __shfl_xor_sync(0xFFFFFFFFu, local, 1);
    if ((tid & 31) == 0 && local) atomicOr(&shit, local);
    __syncthreads();

    // Stage pre-masked tokens for (bl, gl)
    unsigned int hits = shit;
    if (tid < BATCH_PER_GROUP * GENES_PER_BLOCK) {           // 128 threads
        int bl = tid >> 3;                                   // 0..15
        int gl = tid & 7;                                    // 0..7
        int g  = g_base + gl;
        int tok = ((hits >> gl) & 1u) ? (VOCAB - 1)
                                      : X[(b_base + bl) * NUM_GENES + g];
        stok[tid] = tok;
    }
    __syncthreads();

    int gl = tid >> 6;                 // gene within block (0..7)
    int f  = tid & (F4_PER_ROW - 1);   // float4 lane within row
    int g  = g_base + gl;

    float4 a = gene[g * F4_PER_ROW + f];     // register-resident, reused 16x

    long long out_base = (long long)b_base * ROW_STRIDE_F4
                       + g * F4_PER_ROW + f;

    #pragma unroll
    for (int bl = 0; bl < BATCH_PER_GROUP; bl++) {
        int tok = stok[(bl << 3) | gl];            // warp-uniform broadcast
        float4 m = smut[tok * F4_PER_ROW + f];
        float4 o;
        o.x = a.x + m.x;
        o.y = a.y + m.y;
        o.z = a.z + m.z;
        o.w = a.w + m.w;
        __stcs(&out[out_base + (long long)bl * ROW_STRIDE_F4], o);
    }
}

extern "C" void kernel_launch(void* const* d_in, const int* in_sizes, int n_in,
                              void* d_out, int out_size) {
    // metadata order: X_converted, mask_percentage, test_geneset, gene_table, mut_table
    const int*   X        = (const int*)d_in[0];
    const int*   geneset  = (const int*)d_in[2];
    const float* gene     = (const float*)d_in[3];
    const float* mut      = (const float*)d_in[4];
    float*       out      = (float*)d_out;
    int n_mask = in_sizes[2];

    int blocks = GENE_GROUPS * BATCH_GROUPS;     // 5000
    fuse_kernel<<<blocks, THREADS>>>(X,
                                     (const float4*)gene,
                                     (const float4*)mut,
                                     geneset, n_mask,
                                     (float4*)out);
}